// round 15
// baseline (speedup 1.0000x reference)
#include <cuda_runtime.h>
#include <cuda_fp16.h>
#include <mma.h>
#include <math.h>

using namespace nvcuda;

#define NN 50000
#define EE 1600000
#define VV 100000
#define DD 128
#define OO 64
#define TOT (NN*16)
#define NB 49   // ceil(NN/1024)
#define GSB 2368          // grid-stride blocks for gather kernels
#define GST 128           // threads per gather block
#define GSW (GSB*GST/32)  // total warps = 9472

// ---------------- scratch (static device globals; no allocs allowed) ----------
__device__ int    g_cnt[NN];
__device__ int    g_offs[NN + 1];
__device__ int2   g_csr2[EE];       // (src, eid) sorted by dst
__device__ volatile int g_blksum[NB];
__device__ volatile int g_blkflag[NB];
__device__ float  g_isqrt[NN];
__device__ __half g_embh[VV * DD];  // fp16 embedding table
__device__ __half g_xh[NN * DD];    // embedding output (fp16)
__device__ __half g_y[NN * DD];     // pre-scaled GEMM output (y' = isqrt*y)
__device__ __half g_hh[NN * DD];    // relu layer-1 output (fp16)
__device__ __half g_zh[NN * OO];    // z (fp16)
__device__ __half g_w1h[DD * DD];   // W1 fp16
__device__ __half g_wabh[DD * DD];  // [Wmu|Wls] fp16

// ---------------- CSR build ---------------------------------------------------
__global__ void k_hist(const int* __restrict__ dst) {
    int base = (blockIdx.x * blockDim.x + threadIdx.x) * 8;
    if (base + 8 <= EE) {
        int4 d0 = *(const int4*)(dst + base);
        int4 d1 = *(const int4*)(dst + base + 4);
        atomicAdd(&g_cnt[d0.x], 1);
        atomicAdd(&g_cnt[d0.y], 1);
        atomicAdd(&g_cnt[d0.z], 1);
        atomicAdd(&g_cnt[d0.w], 1);
        atomicAdd(&g_cnt[d1.x], 1);
        atomicAdd(&g_cnt[d1.y], 1);
        atomicAdd(&g_cnt[d1.z], 1);
        atomicAdd(&g_cnt[d1.w], 1);
    } else {
        for (int e = base; e < EE; e++) atomicAdd(&g_cnt[dst[e]], 1);
    }
}

// single-kernel chained scan with PARALLEL lookback (49 resident blocks)
__global__ __launch_bounds__(1024) void k_scan() {
    __shared__ int s[1024];
    __shared__ int pre_s[64];
    int t = threadIdx.x, b = blockIdx.x;
    int i = b * 1024 + t;
    int v = (i < NN) ? g_cnt[i] : 0;
    s[t] = v;
    if (t < 64) pre_s[t] = 0;
    __syncthreads();
    #pragma unroll
    for (int off = 1; off < 1024; off <<= 1) {
        int u = (t >= off) ? s[t - off] : 0;
        __syncthreads();
        s[t] += u;
        __syncthreads();
    }
    if (t == 1023) {
        g_blksum[b] = s[1023];
        __threadfence();
        g_blkflag[b] = 1;
    }
    if (t < b) {
        while (g_blkflag[t] == 0) { }
        pre_s[t] = g_blksum[t];
    }
    __syncthreads();
    if (t < 32) {
        int a = pre_s[t] + pre_s[t + 32];
        #pragma unroll
        for (int o = 16; o > 0; o >>= 1) a += __shfl_down_sync(0xffffffffu, a, o);
        if (t == 0) pre_s[0] = a;
    }
    __syncthreads();
    int spre = pre_s[0];
    if (i < NN) {
        g_offs[i] = spre + s[t] - v;
        float deg = (float)(v + 1);
        g_isqrt[i] = rsqrtf(deg);
        g_cnt[i]   = 0;
        if (i == 0) g_offs[NN] = EE;
    }
}

__global__ void k_scatter(const int* __restrict__ src, const int* __restrict__ dst) {
    int base = (blockIdx.x * blockDim.x + threadIdx.x) * 4;
    if (base + 4 <= EE) {
        int4 d = *(const int4*)(dst + base);
        int4 s = *(const int4*)(src + base);
        int p0 = g_offs[d.x] + atomicAdd(&g_cnt[d.x], 1);
        int p1 = g_offs[d.y] + atomicAdd(&g_cnt[d.y], 1);
        int p2 = g_offs[d.z] + atomicAdd(&g_cnt[d.z], 1);
        int p3 = g_offs[d.w] + atomicAdd(&g_cnt[d.w], 1);
        g_csr2[p0] = make_int2(s.x, base);
        g_csr2[p1] = make_int2(s.y, base + 1);
        g_csr2[p2] = make_int2(s.z, base + 2);
        g_csr2[p3] = make_int2(s.w, base + 3);
    } else {
        for (int e = base; e < EE; e++) {
            int d = dst[e];
            int pos = g_offs[d] + atomicAdd(&g_cnt[d], 1);
            g_csr2[pos] = make_int2(src[e], e);
        }
    }
}

// ---------------- fused fp16 conversion: weights + embedding table ------------
__global__ __launch_bounds__(256) void k_cvtall(const float* __restrict__ emb,
                                                const float* __restrict__ W1,
                                                const float* __restrict__ Wmu,
                                                const float* __restrict__ Wls) {
    int i = blockIdx.x * 256 + threadIdx.x;          // float4 index
    if (i < VV * DD / 4) {
        float4 v = ((const float4*)emb)[i];
        __half2 h0 = __floats2half2_rn(v.x, v.y);
        __half2 h1 = __floats2half2_rn(v.z, v.w);
        uint2 u;
        u.x = *(unsigned*)&h0;
        u.y = *(unsigned*)&h1;
        ((uint2*)g_embh)[i] = u;
    }
    if (i < DD * DD / 4) {
        float4 v = ((const float4*)W1)[i];
        __half2 h0 = __floats2half2_rn(v.x, v.y);
        __half2 h1 = __floats2half2_rn(v.z, v.w);
        uint2 u;
        u.x = *(unsigned*)&h0;
        u.y = *(unsigned*)&h1;
        ((uint2*)g_w1h)[i] = u;
    } else if (i < 2 * DD * DD / 4) {
        int j = i - DD * DD / 4;
        int r = j >> 5, c4 = j & 31;
        float4 v;
        if (c4 < 16) v = ((const float4*)Wmu)[r * 16 + c4];
        else         v = ((const float4*)Wls)[r * 16 + (c4 - 16)];
        __half2 h0 = __floats2half2_rn(v.x, v.y);
        __half2 h1 = __floats2half2_rn(v.z, v.w);
        uint2 u;
        u.x = *(unsigned*)&h0;
        u.y = *(unsigned*)&h1;
        ((uint2*)g_wabh)[j] = u;
    }
}

// ---------------- EmbeddingBag(sum, weighted) + L2 normalize -> fp16 ----------
// grid-stride over nodes; 16 gathers in flight per warp
__global__ __launch_bounds__(GST) void k_embed(const int* __restrict__ fidx,
                                               const int* __restrict__ foff,
                                               const float* __restrict__ fw) {
    int wid0 = (blockIdx.x * GST + threadIdx.x) >> 5;
    int lane = threadIdx.x & 31;
    const uint2* emb2 = (const uint2*)g_embh;
    for (int w = wid0; w < NN; w += GSW) {
        int start = foff[w];
        int end = (w + 1 < NN) ? foff[w + 1] : TOT;
        float4 acc = make_float4(0.f, 0.f, 0.f, 0.f);
        if (end - start == 16) {
            int idx[16];
            float wt[16];
            uint2 vv[16];
            #pragma unroll
            for (int q = 0; q < 16; q++) idx[q] = fidx[start + q];
            #pragma unroll
            for (int q = 0; q < 16; q++) wt[q] = fw[start + q];
            #pragma unroll
            for (int q = 0; q < 16; q++) vv[q] = emb2[idx[q] * 32 + lane];
            #pragma unroll
            for (int q = 0; q < 16; q++) {
                float2 f0 = __half22float2(*(__half2*)&vv[q].x);
                float2 f1 = __half22float2(*(__half2*)&vv[q].y);
                acc.x = fmaf(wt[q], f0.x, acc.x);
                acc.y = fmaf(wt[q], f0.y, acc.y);
                acc.z = fmaf(wt[q], f1.x, acc.z);
                acc.w = fmaf(wt[q], f1.y, acc.w);
            }
        } else {
            for (int k = start; k < end; k++) {
                int idx = fidx[k];
                float wt = fw[k];
                uint2 v = emb2[idx * 32 + lane];
                float2 f0 = __half22float2(*(__half2*)&v.x);
                float2 f1 = __half22float2(*(__half2*)&v.y);
                acc.x = fmaf(wt, f0.x, acc.x);
                acc.y = fmaf(wt, f0.y, acc.y);
                acc.z = fmaf(wt, f1.x, acc.z);
                acc.w = fmaf(wt, f1.y, acc.w);
            }
        }
        float ss = acc.x * acc.x + acc.y * acc.y + acc.z * acc.z + acc.w * acc.w;
        for (int o = 16; o > 0; o >>= 1) ss += __shfl_xor_sync(0xffffffffu, ss, o);
        float inv = 1.0f / fmaxf(sqrtf(ss), 1e-12f);
        __half2 h0 = __floats2half2_rn(acc.x * inv, acc.y * inv);
        __half2 h1 = __floats2half2_rn(acc.z * inv, acc.w * inv);
        uint2 u;
        u.x = *(unsigned*)&h0;
        u.y = *(unsigned*)&h1;
        ((uint2*)g_xh)[w * 32 + lane] = u;
    }
}

// ---------------- HMMA GEMM with isqrt-prescaled epilogue ---------------------
__global__ __launch_bounds__(256) void k_gemmA(const __half* __restrict__ A,
                                               const __half* __restrict__ B,
                                               __half* __restrict__ Y) {
    __shared__ __align__(32) char smraw[49152];
    __half* sA = (__half*)smraw;
    __half* sB = (__half*)(smraw + 16384);
    float (*sC)[16][68] = reinterpret_cast<float(*)[16][68]>(smraw);

    int t = threadIdx.x;
    int row0 = blockIdx.x * 64;

    #pragma unroll
    for (int q = 0; q < 4; q++) {
        int idx = t + q * 256;
        int r = idx >> 4, c4 = idx & 15;
        int gr = row0 + r;
        uint4 v = make_uint4(0u, 0u, 0u, 0u);
        if (gr < NN) v = ((const uint4*)A)[gr * 16 + c4];
        ((uint4*)sA)[idx] = v;
    }
    #pragma unroll
    for (int q = 0; q < 8; q++) {
        int idx = t + q * 256;
        ((uint4*)sB)[idx] = ((const uint4*)B)[idx];
    }
    __syncthreads();

    int w = t >> 5, lane = t & 31;
    int wr = w >> 1, wc = w & 1;

    wmma::fragment<wmma::accumulator, 16, 16, 16, float> c[4];
    #pragma unroll
    for (int j = 0; j < 4; j++) wmma::fill_fragment(c[j], 0.f);

    #pragma unroll
    for (int k0 = 0; k0 < 8; k0++) {
        wmma::fragment<wmma::matrix_a, 16, 16, 16, half, wmma::row_major> a;
        wmma::load_matrix_sync(a, sA + (wr * 16) * 128 + k0 * 16, 128);
        #pragma unroll
        for (int j = 0; j < 4; j++) {
            wmma::fragment<wmma::matrix_b, 16, 16, 16, half, wmma::row_major> b;
            wmma::load_matrix_sync(b, sB + (k0 * 16) * 128 + wc * 64 + j * 16, 128);
            wmma::mma_sync(c[j], a, b, c[j]);
        }
    }
    __syncthreads();

    #pragma unroll
    for (int j = 0; j < 4; j++)
        wmma::store_matrix_sync(&sC[w][0][j * 16], c[j], 68, wmma::mem_row_major);
    __syncwarp();
    int r = lane >> 1, ch = (lane & 1) * 32;
    int gr = row0 + wr * 16 + r;
    int col0 = wc * 64;
    if (gr < NN) {
        float sc = g_isqrt[gr];
        __align__(16) __half tmp[32];
        #pragma unroll
        for (int cc = 0; cc < 32; cc++)
            tmp[cc] = __float2half(sC[w][r][ch + cc] * sc);
        uint4* dstp = (uint4*)(Y + (size_t)gr * 128 + col0 + ch);
        const uint4* srcp = (const uint4*)tmp;
        #pragma unroll
        for (int q = 0; q < 4; q++) dstp[q] = srcp[q];
    }
}

// ---------------- gather core: out = isqrt_n * (sum_j y'_j + y'_n) -------------
__device__ __forceinline__ float4 agg_core(const uint2* __restrict__ in2, int n, int lane) {
    int lo = g_offs[n], hi = g_offs[n + 1];
    float4 acc = make_float4(0.f, 0.f, 0.f, 0.f);
    int p = lo;
    for (; p + 16 <= hi; p += 16) {
        int j[16];
        uint2 u[16];
        #pragma unroll
        for (int q = 0; q < 16; q++) j[q] = g_csr2[p + q].x;
        #pragma unroll
        for (int q = 0; q < 16; q++) u[q] = in2[j[q] * 32 + lane];
        #pragma unroll
        for (int q = 0; q < 16; q++) {
            float2 f0 = __half22float2(*(__half2*)&u[q].x);
            float2 f1 = __half22float2(*(__half2*)&u[q].y);
            acc.x += f0.x;
            acc.y += f0.y;
            acc.z += f1.x;
            acc.w += f1.y;
        }
    }
    for (; p + 8 <= hi; p += 8) {
        int j[8];
        uint2 u[8];
        #pragma unroll
        for (int q = 0; q < 8; q++) j[q] = g_csr2[p + q].x;
        #pragma unroll
        for (int q = 0; q < 8; q++) u[q] = in2[j[q] * 32 + lane];
        #pragma unroll
        for (int q = 0; q < 8; q++) {
            float2 f0 = __half22float2(*(__half2*)&u[q].x);
            float2 f1 = __half22float2(*(__half2*)&u[q].y);
            acc.x += f0.x;
            acc.y += f0.y;
            acc.z += f1.x;
            acc.w += f1.y;
        }
    }
    for (; p < hi; p++) {
        int jj = g_csr2[p].x;
        uint2 u = in2[jj * 32 + lane];
        float2 f0 = __half22float2(*(__half2*)&u.x);
        float2 f1 = __half22float2(*(__half2*)&u.y);
        acc.x += f0.x;
        acc.y += f0.y;
        acc.z += f1.x;
        acc.w += f1.y;
    }
    uint2 us = in2[n * 32 + lane];
    float2 s0 = __half22float2(*(__half2*)&us.x);
    float2 s1 = __half22float2(*(__half2*)&us.y);
    float si = g_isqrt[n];
    float4 o;
    o.x = (acc.x + s0.x) * si;
    o.y = (acc.y + s0.y) * si;
    o.z = (acc.z + s1.x) * si;
    o.w = (acc.w + s1.y) * si;
    return o;
}

// ---------------- agg + relu epilogue (grid-stride) ----------------------------
__global__ __launch_bounds__(GST) void k_aggrelu(const __half* __restrict__ in,
                                                 const float* __restrict__ b,
                                                 __half* __restrict__ out) {
    int wid0 = (blockIdx.x * GST + threadIdx.x) >> 5;
    int lane = threadIdx.x & 31;
    float4 bv = ((const float4*)b)[lane];
    for (int w = wid0; w < NN; w += GSW) {
        float4 o = agg_core((const uint2*)in, w, lane);
        o.x = fmaxf(o.x + bv.x, 0.f);
        o.y = fmaxf(o.y + bv.y, 0.f);
        o.z = fmaxf(o.z + bv.z, 0.f);
        o.w = fmaxf(o.w + bv.w, 0.f);
        __half2 h0 = __floats2half2_rn(o.x, o.y);
        __half2 h1 = __floats2half2_rn(o.z, o.w);
        uint2 u;
        u.x = *(unsigned*)&h0;
        u.y = *(unsigned*)&h1;
        ((uint2*)out)[w * 32 + lane] = u;
    }
}

// ---------------- agg + z epilogue (grid-stride) -------------------------------
__global__ __launch_bounds__(GST) void k_aggz(const __half* __restrict__ in,
                                              const float* __restrict__ bmu,
                                              const float* __restrict__ bls,
                                              const float* __restrict__ noise) {
    int wid0 = (blockIdx.x * GST + threadIdx.x) >> 5;
    int lane = threadIdx.x & 31;
    for (int w = wid0; w < NN; w += GSW) {
        float4 o = agg_core((const uint2*)in, w, lane);
        float4 e = make_float4(0.f, 0.f, 0.f, 0.f);
        if (lane >= 16) {
            float4 bv = ((const float4*)bls)[lane - 16];
            float4 nv = ((const float4*)(noise + (size_t)w * 64))[lane - 16];
            e.x = expf(o.x + bv.x) * nv.x;
            e.y = expf(o.y + bv.y) * nv.y;
            e.z = expf(o.z + bv.z) * nv.z;
            e.w = expf(o.w + bv.w) * nv.w;
        }
        e.x = __shfl_down_sync(0xffffffffu, e.x, 16);
        e.y = __shfl_down_sync(0xffffffffu, e.y, 16);
        e.z = __shfl_down_sync(0xffffffffu, e.z, 16);
        e.w = __shfl_down_sync(0xffffffffu, e.w, 16);
        if (lane < 16) {
            float4 bv = ((const float4*)bmu)[lane];
            float zx = o.x + bv.x + e.x;
            float zy = o.y + bv.y + e.y;
            float zz = o.z + bv.z + e.z;
            float zw = o.w + bv.w + e.w;
            __half2 h0 = __floats2half2_rn(zx, zy);
            __half2 h1 = __floats2half2_rn(zz, zw);
            uint2 u;
            u.x = *(unsigned*)&h0;
            u.y = *(unsigned*)&h1;
            ((uint2*)g_zh)[w * 16 + lane] = u;
        }
    }
}

// ---------------- decoder (grid-stride, 2 rows in flight per group) ------------
__global__ __launch_bounds__(GST) void k_dec(float* __restrict__ out) {
    int gid = blockIdx.x * GST + threadIdx.x;
    for (int i = gid; i < NN; i += GSB * GST) g_cnt[i] = 0;
    if (gid < NB) g_blkflag[gid] = 0;

    int wid0 = gid >> 5;
    int lane = threadIdx.x & 31;
    int g = lane >> 3, sl = lane & 7;
    unsigned gm = 0xffu << (g * 8);

    for (int n = wid0; n < NN; n += GSW) {
        int lo = g_offs[n], hi = g_offs[n + 1];
        uint4 zd = ((const uint4*)g_zh)[n * 8 + sl];
        float2 d0 = __half22float2(*(__half2*)&zd.x);
        float2 d1 = __half22float2(*(__half2*)&zd.y);
        float2 d2 = __half22float2(*(__half2*)&zd.z);
        float2 d3 = __half22float2(*(__half2*)&zd.w);

        for (int p = lo + g; p < hi; p += 8) {
            int pB = p + 4;
            bool hB = pB < hi;
            int2 eA = g_csr2[p];
            int2 eB = hB ? g_csr2[pB] : make_int2(0, 0);
            uint4 zA = ((const uint4*)g_zh)[eA.x * 8 + sl];
            uint4 zB = hB ? ((const uint4*)g_zh)[eB.x * 8 + sl] : make_uint4(0u, 0u, 0u, 0u);

            float2 a0 = __half22float2(*(__half2*)&zA.x);
            float2 a1 = __half22float2(*(__half2*)&zA.y);
            float2 a2 = __half22float2(*(__half2*)&zA.z);
            float2 a3 = __half22float2(*(__half2*)&zA.w);
            float vA = a0.x * d0.x + a0.y * d0.y + a1.x * d1.x + a1.y * d1.y
                     + a2.x * d2.x + a2.y * d2.y + a3.x * d3.x + a3.y * d3.y;

            float2 b0 = __half22float2(*(__half2*)&zB.x);
            float2 b1 = __half22float2(*(__half2*)&zB.y);
            float2 b2 = __half22float2(*(__half2*)&zB.z);
            float2 b3 = __half22float2(*(__half2*)&zB.w);
            float vB = b0.x * d0.x + b0.y * d0.y + b1.x * d1.x + b1.y * d1.y
                     + b2.x * d2.x + b2.y * d2.y + b3.x * d3.x + b3.y * d3.y;

            vA += __shfl_xor_sync(gm, vA, 4);
            vA += __shfl_xor_sync(gm, vA, 2);
            vA += __shfl_xor_sync(gm, vA, 1);
            vB += __shfl_xor_sync(gm, vB, 4);
            vB += __shfl_xor_sync(gm, vB, 2);
            vB += __shfl_xor_sync(gm, vB, 1);
            if (sl == 0) {
                out[eA.y] = vA;
                if (hB) out[eB.y] = vB;
            }
        }
    }
}

// ---------------- launch -------------------------------------------------------
extern "C" void kernel_launch(void* const* d_in, const int* in_sizes, int n_in,
                              void* d_out, int out_size) {
    const int*   fidx  = (const int*)d_in[0];
    const int*   foff  = (const int*)d_in[1];
    const float* fw    = (const float*)d_in[2];
    const int*   edge  = (const int*)d_in[3];
    const float* noise = (const float*)d_in[4];
    const float* emb   = (const float*)d_in[5];
    const float* W1    = (const float*)d_in[6];
    const float* b1    = (const float*)d_in[7];
    const float* Wmu   = (const float*)d_in[8];
    const float* bmu   = (const float*)d_in[9];
    const float* Wls   = (const float*)d_in[10];
    const float* bls   = (const float*)d_in[11];
    float* out = (float*)d_out;

    const int* src = edge;
    const int* dst = edge + EE;

    __half *pxh = nullptr, *py = nullptr, *phh = nullptr, *pw1 = nullptr, *pwab = nullptr;
    cudaGetSymbolAddress((void**)&pxh, g_xh);
    cudaGetSymbolAddress((void**)&py, g_y);
    cudaGetSymbolAddress((void**)&phh, g_hh);
    cudaGetSymbolAddress((void**)&pw1, g_w1h);
    cudaGetSymbolAddress((void**)&pwab, g_wabh);

    static cudaStream_t s2 = nullptr;
    static cudaEvent_t evF = nullptr, evS = nullptr, evJ = nullptr;
    static bool ok = false;
    if (!s2) {
        ok = (cudaStreamCreateWithFlags(&s2, cudaStreamNonBlocking) == cudaSuccess) &&
             (cudaEventCreateWithFlags(&evF, cudaEventDisableTiming) == cudaSuccess) &&
             (cudaEventCreateWithFlags(&evS, cudaEventDisableTiming) == cudaSuccess) &&
             (cudaEventCreateWithFlags(&evJ, cudaEventDisableTiming) == cudaSuccess);
    }

    if (!ok) {
        k_hist<<<(EE / 8 + 255) / 256, 256>>>(dst);
        k_scan<<<NB, 1024>>>();
        k_scatter<<<(EE / 4 + 255) / 256, 256>>>(src, dst);
        k_cvtall<<<(VV * DD / 4 + 255) / 256, 256>>>(emb, W1, Wmu, Wls);
        k_embed<<<GSB, GST>>>(fidx, foff, fw);
        k_gemmA<<<(NN + 63) / 64, 256>>>(pxh, pw1, py);
        k_aggrelu<<<GSB, GST>>>(py, b1, phh);
        k_gemmA<<<(NN + 63) / 64, 256>>>(phh, pwab, py);
        k_aggz<<<GSB, GST>>>(py, bmu, bls, noise);
        k_dec<<<GSB, GST>>>(out);
        return;
    }

    // fork
    cudaEventRecord(evF, 0);
    cudaStreamWaitEvent(s2, evF, 0);

    // branch B (s2): fp16 conversions + embedding (no CSR dependence)
    k_cvtall<<<(VV * DD / 4 + 255) / 256, 256, 0, s2>>>(emb, W1, Wmu, Wls);
    k_embed<<<GSB, GST, 0, s2>>>(fidx, foff, fw);

    // branch A (default): hist + scan (produces isqrt), then scatter
    k_hist<<<(EE / 8 + 255) / 256, 256>>>(dst);
    k_scan<<<NB, 1024>>>();
    cudaEventRecord(evS, 0);                 // isqrt ready
    k_scatter<<<(EE / 4 + 255) / 256, 256>>>(src, dst);

    // branch B continues: gemm1' needs isqrt (prescaled epilogue)
    cudaStreamWaitEvent(s2, evS, 0);
    k_gemmA<<<(NN + 63) / 64, 256, 0, s2>>>(pxh, pw1, py);   // y1' = isqrt*(x@W1)
    cudaEventRecord(evJ, s2);

    // join, then the serial back half
    cudaStreamWaitEvent(0, evJ, 0);
    k_aggrelu<<<GSB, GST>>>(py, b1, phh);                    // h = relu(agg(y1')+b1)
    k_gemmA<<<(NN + 63) / 64, 256>>>(phh, pwab, py);         // y2' = isqrt*(h@[Wmu|Wls])
    k_aggz<<<GSB, GST>>>(py, bmu, bls, noise);               // z
    k_dec<<<GSB, GST>>>(out);
}

// round 16
// speedup vs baseline: 1.0573x; 1.0573x over previous
#include <cuda_runtime.h>
#include <cuda_fp16.h>
#include <mma.h>
#include <math.h>

using namespace nvcuda;

#define NN 50000
#define EE 1600000
#define VV 100000
#define DD 128
#define OO 64
#define TOT (NN*16)
#define NB 49   // ceil(NN/1024)

// ---------------- scratch (static device globals; no allocs allowed) ----------
__device__ int    g_cnt[NN];
__device__ int    g_offs[NN + 1];
__device__ int2   g_csr2[EE];       // (src, eid) sorted by dst
__device__ volatile int g_blksum[NB];
__device__ volatile int g_blkflag[NB];
__device__ float  g_isqrt[NN];
__device__ __half g_embh[VV * DD];  // fp16 embedding table
__device__ __half g_xh[NN * DD];    // embedding output (fp16)
__device__ __half g_y[NN * DD];     // pre-scaled GEMM output (y' = isqrt*y)
__device__ __half g_hh[NN * DD];    // relu layer-1 output (fp16)
__device__ __half g_zh[NN * OO];    // z (fp16)
__device__ __half g_w1h[DD * DD];   // W1 fp16
__device__ __half g_wabh[DD * DD];  // [Wmu|Wls] fp16

// ---------------- CSR build ---------------------------------------------------
__global__ void k_hist(const int* __restrict__ dst) {
    int base = (blockIdx.x * blockDim.x + threadIdx.x) * 4;
    if (base + 4 <= EE) {
        int4 d = *(const int4*)(dst + base);
        atomicAdd(&g_cnt[d.x], 1);
        atomicAdd(&g_cnt[d.y], 1);
        atomicAdd(&g_cnt[d.z], 1);
        atomicAdd(&g_cnt[d.w], 1);
    } else {
        for (int e = base; e < EE; e++) atomicAdd(&g_cnt[dst[e]], 1);
    }
}

// single-kernel chained scan with PARALLEL lookback (49 resident blocks)
__global__ __launch_bounds__(1024) void k_scan() {
    __shared__ int s[1024];
    __shared__ int pre_s[64];
    int t = threadIdx.x, b = blockIdx.x;
    int i = b * 1024 + t;
    int v = (i < NN) ? g_cnt[i] : 0;
    s[t] = v;
    if (t < 64) pre_s[t] = 0;
    __syncthreads();
    #pragma unroll
    for (int off = 1; off < 1024; off <<= 1) {
        int u = (t >= off) ? s[t - off] : 0;
        __syncthreads();
        s[t] += u;
        __syncthreads();
    }
    if (t == 1023) {
        g_blksum[b] = s[1023];
        __threadfence();
        g_blkflag[b] = 1;
    }
    if (t < b) {
        while (g_blkflag[t] == 0) { }
        pre_s[t] = g_blksum[t];
    }
    __syncthreads();
    if (t < 32) {
        int a = pre_s[t] + pre_s[t + 32];
        #pragma unroll
        for (int o = 16; o > 0; o >>= 1) a += __shfl_down_sync(0xffffffffu, a, o);
        if (t == 0) pre_s[0] = a;
    }
    __syncthreads();
    int spre = pre_s[0];
    if (i < NN) {
        g_offs[i] = spre + s[t] - v;
        float deg = (float)(v + 1);
        g_isqrt[i] = rsqrtf(deg);
        g_cnt[i]   = 0;
        if (i == 0) g_offs[NN] = EE;
    }
}

__global__ void k_scatter(const int* __restrict__ src, const int* __restrict__ dst) {
    int base = (blockIdx.x * blockDim.x + threadIdx.x) * 4;
    if (base + 4 <= EE) {
        int4 d = *(const int4*)(dst + base);
        int4 s = *(const int4*)(src + base);
        int p0 = g_offs[d.x] + atomicAdd(&g_cnt[d.x], 1);
        int p1 = g_offs[d.y] + atomicAdd(&g_cnt[d.y], 1);
        int p2 = g_offs[d.z] + atomicAdd(&g_cnt[d.z], 1);
        int p3 = g_offs[d.w] + atomicAdd(&g_cnt[d.w], 1);
        g_csr2[p0] = make_int2(s.x, base);
        g_csr2[p1] = make_int2(s.y, base + 1);
        g_csr2[p2] = make_int2(s.z, base + 2);
        g_csr2[p3] = make_int2(s.w, base + 3);
    } else {
        for (int e = base; e < EE; e++) {
            int d = dst[e];
            int pos = g_offs[d] + atomicAdd(&g_cnt[d], 1);
            g_csr2[pos] = make_int2(src[e], e);
        }
    }
}

// ---------------- fused fp16 conversion: weights + embedding table ------------
__global__ __launch_bounds__(256) void k_cvtall(const float* __restrict__ emb,
                                                const float* __restrict__ W1,
                                                const float* __restrict__ Wmu,
                                                const float* __restrict__ Wls) {
    int i = blockIdx.x * 256 + threadIdx.x;          // float4 index
    if (i < VV * DD / 4) {
        float4 v = ((const float4*)emb)[i];
        __half2 h0 = __floats2half2_rn(v.x, v.y);
        __half2 h1 = __floats2half2_rn(v.z, v.w);
        uint2 u;
        u.x = *(unsigned*)&h0;
        u.y = *(unsigned*)&h1;
        ((uint2*)g_embh)[i] = u;
    }
    if (i < DD * DD / 4) {
        float4 v = ((const float4*)W1)[i];
        __half2 h0 = __floats2half2_rn(v.x, v.y);
        __half2 h1 = __floats2half2_rn(v.z, v.w);
        uint2 u;
        u.x = *(unsigned*)&h0;
        u.y = *(unsigned*)&h1;
        ((uint2*)g_w1h)[i] = u;
    } else if (i < 2 * DD * DD / 4) {
        int j = i - DD * DD / 4;
        int r = j >> 5, c4 = j & 31;
        float4 v;
        if (c4 < 16) v = ((const float4*)Wmu)[r * 16 + c4];
        else         v = ((const float4*)Wls)[r * 16 + (c4 - 16)];
        __half2 h0 = __floats2half2_rn(v.x, v.y);
        __half2 h1 = __floats2half2_rn(v.z, v.w);
        uint2 u;
        u.x = *(unsigned*)&h0;
        u.y = *(unsigned*)&h1;
        ((uint2*)g_wabh)[j] = u;
    }
}

// ---------------- EmbeddingBag(sum, weighted) + L2 normalize -> fp16 ----------
// one warp per node; 16 gathers in flight per warp
__global__ void k_embed(const int* __restrict__ fidx, const int* __restrict__ foff,
                        const float* __restrict__ fw) {
    int w = (blockIdx.x * blockDim.x + threadIdx.x) >> 5;
    int lane = threadIdx.x & 31;
    if (w >= NN) return;
    int start = foff[w];
    int end = (w + 1 < NN) ? foff[w + 1] : TOT;
    const uint2* emb2 = (const uint2*)g_embh;
    float4 acc = make_float4(0.f, 0.f, 0.f, 0.f);
    if (end - start == 16) {
        int idx[16];
        float wt[16];
        uint2 vv[16];
        #pragma unroll
        for (int q = 0; q < 16; q++) idx[q] = fidx[start + q];
        #pragma unroll
        for (int q = 0; q < 16; q++) wt[q] = fw[start + q];
        #pragma unroll
        for (int q = 0; q < 16; q++) vv[q] = emb2[idx[q] * 32 + lane];
        #pragma unroll
        for (int q = 0; q < 16; q++) {
            float2 f0 = __half22float2(*(__half2*)&vv[q].x);
            float2 f1 = __half22float2(*(__half2*)&vv[q].y);
            acc.x = fmaf(wt[q], f0.x, acc.x);
            acc.y = fmaf(wt[q], f0.y, acc.y);
            acc.z = fmaf(wt[q], f1.x, acc.z);
            acc.w = fmaf(wt[q], f1.y, acc.w);
        }
    } else {
        for (int k = start; k < end; k++) {
            int idx = fidx[k];
            float wt = fw[k];
            uint2 v = emb2[idx * 32 + lane];
            float2 f0 = __half22float2(*(__half2*)&v.x);
            float2 f1 = __half22float2(*(__half2*)&v.y);
            acc.x = fmaf(wt, f0.x, acc.x);
            acc.y = fmaf(wt, f0.y, acc.y);
            acc.z = fmaf(wt, f1.x, acc.z);
            acc.w = fmaf(wt, f1.y, acc.w);
        }
    }
    float ss = acc.x * acc.x + acc.y * acc.y + acc.z * acc.z + acc.w * acc.w;
    for (int o = 16; o > 0; o >>= 1) ss += __shfl_xor_sync(0xffffffffu, ss, o);
    float inv = 1.0f / fmaxf(sqrtf(ss), 1e-12f);
    __half2 h0 = __floats2half2_rn(acc.x * inv, acc.y * inv);
    __half2 h1 = __floats2half2_rn(acc.z * inv, acc.w * inv);
    uint2 u;
    u.x = *(unsigned*)&h0;
    u.y = *(unsigned*)&h1;
    ((uint2*)g_xh)[w * 32 + lane] = u;
}

// ---------------- HMMA GEMM with isqrt-prescaled epilogue ---------------------
__global__ __launch_bounds__(256) void k_gemmA(const __half* __restrict__ A,
                                               const __half* __restrict__ B,
                                               __half* __restrict__ Y) {
    __shared__ __align__(32) char smraw[49152];
    __half* sA = (__half*)smraw;
    __half* sB = (__half*)(smraw + 16384);
    float (*sC)[16][68] = reinterpret_cast<float(*)[16][68]>(smraw);

    int t = threadIdx.x;
    int row0 = blockIdx.x * 64;

    #pragma unroll
    for (int q = 0; q < 4; q++) {
        int idx = t + q * 256;
        int r = idx >> 4, c4 = idx & 15;
        int gr = row0 + r;
        uint4 v = make_uint4(0u, 0u, 0u, 0u);
        if (gr < NN) v = ((const uint4*)A)[gr * 16 + c4];
        ((uint4*)sA)[idx] = v;
    }
    #pragma unroll
    for (int q = 0; q < 8; q++) {
        int idx = t + q * 256;
        ((uint4*)sB)[idx] = ((const uint4*)B)[idx];
    }
    __syncthreads();

    int w = t >> 5, lane = t & 31;
    int wr = w >> 1, wc = w & 1;

    wmma::fragment<wmma::accumulator, 16, 16, 16, float> c[4];
    #pragma unroll
    for (int j = 0; j < 4; j++) wmma::fill_fragment(c[j], 0.f);

    #pragma unroll
    for (int k0 = 0; k0 < 8; k0++) {
        wmma::fragment<wmma::matrix_a, 16, 16, 16, half, wmma::row_major> a;
        wmma::load_matrix_sync(a, sA + (wr * 16) * 128 + k0 * 16, 128);
        #pragma unroll
        for (int j = 0; j < 4; j++) {
            wmma::fragment<wmma::matrix_b, 16, 16, 16, half, wmma::row_major> b;
            wmma::load_matrix_sync(b, sB + (k0 * 16) * 128 + wc * 64 + j * 16, 128);
            wmma::mma_sync(c[j], a, b, c[j]);
        }
    }
    __syncthreads();

    #pragma unroll
    for (int j = 0; j < 4; j++)
        wmma::store_matrix_sync(&sC[w][0][j * 16], c[j], 68, wmma::mem_row_major);
    __syncwarp();
    int r = lane >> 1, ch = (lane & 1) * 32;
    int gr = row0 + wr * 16 + r;
    int col0 = wc * 64;
    if (gr < NN) {
        float sc = g_isqrt[gr];
        __align__(16) __half tmp[32];
        #pragma unroll
        for (int cc = 0; cc < 32; cc++)
            tmp[cc] = __float2half(sC[w][r][ch + cc] * sc);
        uint4* dstp = (uint4*)(Y + (size_t)gr * 128 + col0 + ch);
        const uint4* srcp = (const uint4*)tmp;
        #pragma unroll
        for (int q = 0; q < 4; q++) dstp[q] = srcp[q];
    }
}

// ---------------- gather core: out = isqrt_n * (sum_j y'_j + y'_n) -------------
// 16 row-loads in flight per warp; one warp per node
__device__ __forceinline__ float4 agg_core(const uint2* __restrict__ in2, int n, int lane) {
    int lo = g_offs[n], hi = g_offs[n + 1];
    float4 acc = make_float4(0.f, 0.f, 0.f, 0.f);
    int p = lo;
    for (; p + 16 <= hi; p += 16) {
        int j[16];
        uint2 u[16];
        #pragma unroll
        for (int q = 0; q < 16; q++) j[q] = g_csr2[p + q].x;
        #pragma unroll
        for (int q = 0; q < 16; q++) u[q] = in2[j[q] * 32 + lane];
        #pragma unroll
        for (int q = 0; q < 16; q++) {
            float2 f0 = __half22float2(*(__half2*)&u[q].x);
            float2 f1 = __half22float2(*(__half2*)&u[q].y);
            acc.x += f0.x;
            acc.y += f0.y;
            acc.z += f1.x;
            acc.w += f1.y;
        }
    }
    for (; p + 8 <= hi; p += 8) {
        int j[8];
        uint2 u[8];
        #pragma unroll
        for (int q = 0; q < 8; q++) j[q] = g_csr2[p + q].x;
        #pragma unroll
        for (int q = 0; q < 8; q++) u[q] = in2[j[q] * 32 + lane];
        #pragma unroll
        for (int q = 0; q < 8; q++) {
            float2 f0 = __half22float2(*(__half2*)&u[q].x);
            float2 f1 = __half22float2(*(__half2*)&u[q].y);
            acc.x += f0.x;
            acc.y += f0.y;
            acc.z += f1.x;
            acc.w += f1.y;
        }
    }
    for (; p < hi; p++) {
        int jj = g_csr2[p].x;
        uint2 u = in2[jj * 32 + lane];
        float2 f0 = __half22float2(*(__half2*)&u.x);
        float2 f1 = __half22float2(*(__half2*)&u.y);
        acc.x += f0.x;
        acc.y += f0.y;
        acc.z += f1.x;
        acc.w += f1.y;
    }
    uint2 us = in2[n * 32 + lane];
    float2 s0 = __half22float2(*(__half2*)&us.x);
    float2 s1 = __half22float2(*(__half2*)&us.y);
    float si = g_isqrt[n];
    float4 o;
    o.x = (acc.x + s0.x) * si;
    o.y = (acc.y + s0.y) * si;
    o.z = (acc.z + s1.x) * si;
    o.w = (acc.w + s1.y) * si;
    return o;
}

// ---------------- agg + relu epilogue ------------------------------------------
__global__ void k_aggrelu(const __half* __restrict__ in, const float* __restrict__ b,
                          __half* __restrict__ out) {
    int w = (blockIdx.x * blockDim.x + threadIdx.x) >> 5;
    int lane = threadIdx.x & 31;
    if (w >= NN) return;
    float4 o = agg_core((const uint2*)in, w, lane);
    float4 bv = ((const float4*)b)[lane];
    o.x = fmaxf(o.x + bv.x, 0.f);
    o.y = fmaxf(o.y + bv.y, 0.f);
    o.z = fmaxf(o.z + bv.z, 0.f);
    o.w = fmaxf(o.w + bv.w, 0.f);
    __half2 h0 = __floats2half2_rn(o.x, o.y);
    __half2 h1 = __floats2half2_rn(o.z, o.w);
    uint2 u;
    u.x = *(unsigned*)&h0;
    u.y = *(unsigned*)&h1;
    ((uint2*)out)[w * 32 + lane] = u;
}

// ---------------- agg + z epilogue ---------------------------------------------
__global__ void k_aggz(const __half* __restrict__ in, const float* __restrict__ bmu,
                       const float* __restrict__ bls, const float* __restrict__ noise) {
    int w = (blockIdx.x * blockDim.x + threadIdx.x) >> 5;
    int lane = threadIdx.x & 31;
    if (w >= NN) return;
    float4 o = agg_core((const uint2*)in, w, lane);

    float4 e = make_float4(0.f, 0.f, 0.f, 0.f);
    if (lane >= 16) {
        float4 bv = ((const float4*)bls)[lane - 16];
        float4 nv = ((const float4*)(noise + (size_t)w * 64))[lane - 16];
        e.x = expf(o.x + bv.x) * nv.x;
        e.y = expf(o.y + bv.y) * nv.y;
        e.z = expf(o.z + bv.z) * nv.z;
        e.w = expf(o.w + bv.w) * nv.w;
    }
    e.x = __shfl_down_sync(0xffffffffu, e.x, 16);
    e.y = __shfl_down_sync(0xffffffffu, e.y, 16);
    e.z = __shfl_down_sync(0xffffffffu, e.z, 16);
    e.w = __shfl_down_sync(0xffffffffu, e.w, 16);
    if (lane < 16) {
        float4 bv = ((const float4*)bmu)[lane];
        float zx = o.x + bv.x + e.x;
        float zy = o.y + bv.y + e.y;
        float zz = o.z + bv.z + e.z;
        float zw = o.w + bv.w + e.w;
        __half2 h0 = __floats2half2_rn(zx, zy);
        __half2 h1 = __floats2half2_rn(zz, zw);
        uint2 u;
        u.x = *(unsigned*)&h0;
        u.y = *(unsigned*)&h1;
        ((uint2*)g_zh)[w * 16 + lane] = u;
    }
}

// ---------------- decoder: one warp per dst node; 2 rows in flight -------------
__global__ void k_dec(float* __restrict__ out) {
    int gid = blockIdx.x * blockDim.x + threadIdx.x;
    if (gid < NN) g_cnt[gid] = 0;
    if (gid < NB) g_blkflag[gid] = 0;
    int n = gid >> 5;
    if (n >= NN) return;
    int lane = threadIdx.x & 31;
    int g = lane >> 3, sl = lane & 7;
    unsigned gm = 0xffu << (g * 8);

    int lo = g_offs[n], hi = g_offs[n + 1];
    uint4 zd = ((const uint4*)g_zh)[n * 8 + sl];
    float2 d0 = __half22float2(*(__half2*)&zd.x);
    float2 d1 = __half22float2(*(__half2*)&zd.y);
    float2 d2 = __half22float2(*(__half2*)&zd.z);
    float2 d3 = __half22float2(*(__half2*)&zd.w);

    for (int p = lo + g; p < hi; p += 8) {
        int pB = p + 4;
        bool hB = pB < hi;
        int2 eA = g_csr2[p];
        int2 eB = hB ? g_csr2[pB] : make_int2(0, 0);
        uint4 zA = ((const uint4*)g_zh)[eA.x * 8 + sl];
        uint4 zB = hB ? ((const uint4*)g_zh)[eB.x * 8 + sl] : make_uint4(0u, 0u, 0u, 0u);

        float2 a0 = __half22float2(*(__half2*)&zA.x);
        float2 a1 = __half22float2(*(__half2*)&zA.y);
        float2 a2 = __half22float2(*(__half2*)&zA.z);
        float2 a3 = __half22float2(*(__half2*)&zA.w);
        float vA = a0.x * d0.x + a0.y * d0.y + a1.x * d1.x + a1.y * d1.y
                 + a2.x * d2.x + a2.y * d2.y + a3.x * d3.x + a3.y * d3.y;

        float2 b0 = __half22float2(*(__half2*)&zB.x);
        float2 b1 = __half22float2(*(__half2*)&zB.y);
        float2 b2 = __half22float2(*(__half2*)&zB.z);
        float2 b3 = __half22float2(*(__half2*)&zB.w);
        float vB = b0.x * d0.x + b0.y * d0.y + b1.x * d1.x + b1.y * d1.y
                 + b2.x * d2.x + b2.y * d2.y + b3.x * d3.x + b3.y * d3.y;

        vA += __shfl_xor_sync(gm, vA, 4);
        vA += __shfl_xor_sync(gm, vA, 2);
        vA += __shfl_xor_sync(gm, vA, 1);
        vB += __shfl_xor_sync(gm, vB, 4);
        vB += __shfl_xor_sync(gm, vB, 2);
        vB += __shfl_xor_sync(gm, vB, 1);
        if (sl == 0) {
            out[eA.y] = vA;
            if (hB) out[eB.y] = vB;
        }
    }
}

// ---------------- launch -------------------------------------------------------
extern "C" void kernel_launch(void* const* d_in, const int* in_sizes, int n_in,
                              void* d_out, int out_size) {
    const int*   fidx  = (const int*)d_in[0];
    const int*   foff  = (const int*)d_in[1];
    const float* fw    = (const float*)d_in[2];
    const int*   edge  = (const int*)d_in[3];
    const float* noise = (const float*)d_in[4];
    const float* emb   = (const float*)d_in[5];
    const float* W1    = (const float*)d_in[6];
    const float* b1    = (const float*)d_in[7];
    const float* Wmu   = (const float*)d_in[8];
    const float* bmu   = (const float*)d_in[9];
    const float* Wls   = (const float*)d_in[10];
    const float* bls   = (const float*)d_in[11];
    float* out = (float*)d_out;

    const int* src = edge;
    const int* dst = edge + EE;

    __half *pxh = nullptr, *py = nullptr, *phh = nullptr, *pw1 = nullptr, *pwab = nullptr;
    cudaGetSymbolAddress((void**)&pxh, g_xh);
    cudaGetSymbolAddress((void**)&py, g_y);
    cudaGetSymbolAddress((void**)&phh, g_hh);
    cudaGetSymbolAddress((void**)&pw1, g_w1h);
    cudaGetSymbolAddress((void**)&pwab, g_wabh);

    static cudaStream_t s2 = nullptr;
    static cudaEvent_t evF = nullptr, evS = nullptr, evJ = nullptr;
    static bool ok = false;
    if (!s2) {
        ok = (cudaStreamCreateWithFlags(&s2, cudaStreamNonBlocking) == cudaSuccess) &&
             (cudaEventCreateWithFlags(&evF, cudaEventDisableTiming) == cudaSuccess) &&
             (cudaEventCreateWithFlags(&evS, cudaEventDisableTiming) == cudaSuccess) &&
             (cudaEventCreateWithFlags(&evJ, cudaEventDisableTiming) == cudaSuccess);
    }

    if (!ok) {
        k_hist<<<(EE / 4 + 255) / 256, 256>>>(dst);
        k_scan<<<NB, 1024>>>();
        k_scatter<<<(EE / 4 + 255) / 256, 256>>>(src, dst);
        k_cvtall<<<(VV * DD / 4 + 255) / 256, 256>>>(emb, W1, Wmu, Wls);
        k_embed<<<(NN + 3) / 4, 128>>>(fidx, foff, fw);
        k_gemmA<<<(NN + 63) / 64, 256>>>(pxh, pw1, py);
        k_aggrelu<<<(NN + 3) / 4, 128>>>(py, b1, phh);
        k_gemmA<<<(NN + 63) / 64, 256>>>(phh, pwab, py);
        k_aggz<<<(NN + 3) / 4, 128>>>(py, bmu, bls, noise);
        k_dec<<<(NN * 32 + 255) / 256, 256>>>(out);
        return;
    }

    // fork
    cudaEventRecord(evF, 0);
    cudaStreamWaitEvent(s2, evF, 0);

    // branch B (s2): fp16 conversions + embedding (no CSR dependence)
    k_cvtall<<<(VV * DD / 4 + 255) / 256, 256, 0, s2>>>(emb, W1, Wmu, Wls);
    k_embed<<<(NN + 3) / 4, 128, 0, s2>>>(fidx, foff, fw);

    // branch A (default): hist + scan (produces isqrt), then scatter
    k_hist<<<(EE / 4 + 255) / 256, 256>>>(dst);
    k_scan<<<NB, 1024>>>();
    cudaEventRecord(evS, 0);                 // isqrt ready
    k_scatter<<<(EE / 4 + 255) / 256, 256>>>(src, dst);

    // branch B continues: gemm1' needs isqrt (prescaled epilogue)
    cudaStreamWaitEvent(s2, evS, 0);
    k_gemmA<<<(NN + 63) / 64, 256, 0, s2>>>(pxh, pw1, py);   // y1' = isqrt*(x@W1)
    cudaEventRecord(evJ, s2);

    // join, then the serial back half
    cudaStreamWaitEvent(0, evJ, 0);
    k_aggrelu<<<(NN + 3) / 4, 128>>>(py, b1, phh);           // h = relu(agg(y1')+b1)
    k_gemmA<<<(NN + 63) / 64, 256>>>(phh, pwab, py);         // y2' = isqrt*(h@[Wmu|Wls])
    k_aggz<<<(NN + 3) / 4, 128>>>(py, bmu, bls, noise);      // z
    k_dec<<<(NN * 32 + 255) / 256, 256>>>(out);
}

// round 17
// speedup vs baseline: 1.0663x; 1.0085x over previous
#include <cuda_runtime.h>
#include <cuda_fp16.h>
#include <mma.h>
#include <math.h>

using namespace nvcuda;

#define NN 50000
#define EE 1600000
#define VV 100000
#define DD 128
#define OO 64
#define TOT (NN*16)
#define NB 49   // ceil(NN/1024)

// ---------------- scratch (static device globals; no allocs allowed) ----------
__device__ int    g_cnt[NN];
__device__ int    g_offs[NN + 1];
__device__ int2   g_csr2[EE];       // (src, eid) sorted by dst
__device__ volatile int g_blksum[NB];
__device__ volatile int g_blkflag[NB];
__device__ float  g_isqrt[NN];
__device__ __half g_embh[VV * DD];  // fp16 embedding table
__device__ __half g_xh[NN * DD];    // embedding output (fp16)
__device__ __half g_y[NN * DD];     // pre-scaled GEMM output (y' = isqrt*y)
__device__ __half g_hh[NN * DD];    // relu layer-1 output (fp16)
__device__ __half g_zh[NN * OO];    // z (fp16)
__device__ __half g_w1h[DD * DD];   // W1 fp16
__device__ __half g_wabh[DD * DD];  // [Wmu|Wls] fp16

// ---------------- CSR build ---------------------------------------------------
__global__ void k_hist(const int* __restrict__ dst) {
    int base = (blockIdx.x * blockDim.x + threadIdx.x) * 4;
    if (base + 4 <= EE) {
        int4 d = *(const int4*)(dst + base);
        atomicAdd(&g_cnt[d.x], 1);
        atomicAdd(&g_cnt[d.y], 1);
        atomicAdd(&g_cnt[d.z], 1);
        atomicAdd(&g_cnt[d.w], 1);
    } else {
        for (int e = base; e < EE; e++) atomicAdd(&g_cnt[dst[e]], 1);
    }
}

// single-kernel chained scan with PARALLEL lookback (49 resident blocks)
__global__ __launch_bounds__(1024) void k_scan() {
    __shared__ int s[1024];
    __shared__ int pre_s[64];
    int t = threadIdx.x, b = blockIdx.x;
    int i = b * 1024 + t;
    int v = (i < NN) ? g_cnt[i] : 0;
    s[t] = v;
    if (t < 64) pre_s[t] = 0;
    __syncthreads();
    #pragma unroll
    for (int off = 1; off < 1024; off <<= 1) {
        int u = (t >= off) ? s[t - off] : 0;
        __syncthreads();
        s[t] += u;
        __syncthreads();
    }
    if (t == 1023) {
        g_blksum[b] = s[1023];
        __threadfence();
        g_blkflag[b] = 1;
    }
    if (t < b) {
        while (g_blkflag[t] == 0) { }
        pre_s[t] = g_blksum[t];
    }
    __syncthreads();
    if (t < 32) {
        int a = pre_s[t] + pre_s[t + 32];
        #pragma unroll
        for (int o = 16; o > 0; o >>= 1) a += __shfl_down_sync(0xffffffffu, a, o);
        if (t == 0) pre_s[0] = a;
    }
    __syncthreads();
    int spre = pre_s[0];
    if (i < NN) {
        g_offs[i] = spre + s[t] - v;
        float deg = (float)(v + 1);
        g_isqrt[i] = rsqrtf(deg);
        g_cnt[i]   = 0;
        if (i == 0) g_offs[NN] = EE;
    }
}

__global__ void k_scatter(const int* __restrict__ src, const int* __restrict__ dst) {
    int base = (blockIdx.x * blockDim.x + threadIdx.x) * 4;
    if (base + 4 <= EE) {
        int4 d = *(const int4*)(dst + base);
        int4 s = *(const int4*)(src + base);
        int p0 = g_offs[d.x] + atomicAdd(&g_cnt[d.x], 1);
        int p1 = g_offs[d.y] + atomicAdd(&g_cnt[d.y], 1);
        int p2 = g_offs[d.z] + atomicAdd(&g_cnt[d.z], 1);
        int p3 = g_offs[d.w] + atomicAdd(&g_cnt[d.w], 1);
        g_csr2[p0] = make_int2(s.x, base);
        g_csr2[p1] = make_int2(s.y, base + 1);
        g_csr2[p2] = make_int2(s.z, base + 2);
        g_csr2[p3] = make_int2(s.w, base + 3);
    } else {
        for (int e = base; e < EE; e++) {
            int d = dst[e];
            int pos = g_offs[d] + atomicAdd(&g_cnt[d], 1);
            g_csr2[pos] = make_int2(src[e], e);
        }
    }
}

// ---------------- fused fp16 conversion: weights + embedding table ------------
__global__ __launch_bounds__(256) void k_cvtall(const float* __restrict__ emb,
                                                const float* __restrict__ W1,
                                                const float* __restrict__ Wmu,
                                                const float* __restrict__ Wls) {
    int i = blockIdx.x * 256 + threadIdx.x;          // float4 index
    if (i < VV * DD / 4) {
        float4 v = ((const float4*)emb)[i];
        __half2 h0 = __floats2half2_rn(v.x, v.y);
        __half2 h1 = __floats2half2_rn(v.z, v.w);
        uint2 u;
        u.x = *(unsigned*)&h0;
        u.y = *(unsigned*)&h1;
        ((uint2*)g_embh)[i] = u;
    }
    if (i < DD * DD / 4) {
        float4 v = ((const float4*)W1)[i];
        __half2 h0 = __floats2half2_rn(v.x, v.y);
        __half2 h1 = __floats2half2_rn(v.z, v.w);
        uint2 u;
        u.x = *(unsigned*)&h0;
        u.y = *(unsigned*)&h1;
        ((uint2*)g_w1h)[i] = u;
    } else if (i < 2 * DD * DD / 4) {
        int j = i - DD * DD / 4;
        int r = j >> 5, c4 = j & 31;
        float4 v;
        if (c4 < 16) v = ((const float4*)Wmu)[r * 16 + c4];
        else         v = ((const float4*)Wls)[r * 16 + (c4 - 16)];
        __half2 h0 = __floats2half2_rn(v.x, v.y);
        __half2 h1 = __floats2half2_rn(v.z, v.w);
        uint2 u;
        u.x = *(unsigned*)&h0;
        u.y = *(unsigned*)&h1;
        ((uint2*)g_wabh)[j] = u;
    }
}

// ---------------- EmbeddingBag(sum, weighted) + L2 normalize -> fp16 ----------
__global__ void k_embed(const int* __restrict__ fidx, const int* __restrict__ foff,
                        const float* __restrict__ fw) {
    int w = (blockIdx.x * blockDim.x + threadIdx.x) >> 5;
    int lane = threadIdx.x & 31;
    if (w >= NN) return;
    int start = foff[w];
    int end = (w + 1 < NN) ? foff[w + 1] : TOT;
    const uint2* emb2 = (const uint2*)g_embh;
    float4 acc = make_float4(0.f, 0.f, 0.f, 0.f);
    if (end - start == 16) {
        int idx[16];
        float wt[16];
        uint2 vv[16];
        #pragma unroll
        for (int q = 0; q < 16; q++) idx[q] = fidx[start + q];
        #pragma unroll
        for (int q = 0; q < 16; q++) wt[q] = fw[start + q];
        #pragma unroll
        for (int q = 0; q < 16; q++) vv[q] = emb2[idx[q] * 32 + lane];
        #pragma unroll
        for (int q = 0; q < 16; q++) {
            float2 f0 = __half22float2(*(__half2*)&vv[q].x);
            float2 f1 = __half22float2(*(__half2*)&vv[q].y);
            acc.x = fmaf(wt[q], f0.x, acc.x);
            acc.y = fmaf(wt[q], f0.y, acc.y);
            acc.z = fmaf(wt[q], f1.x, acc.z);
            acc.w = fmaf(wt[q], f1.y, acc.w);
        }
    } else {
        for (int k = start; k < end; k++) {
            int idx = fidx[k];
            float wt = fw[k];
            uint2 v = emb2[idx * 32 + lane];
            float2 f0 = __half22float2(*(__half2*)&v.x);
            float2 f1 = __half22float2(*(__half2*)&v.y);
            acc.x = fmaf(wt, f0.x, acc.x);
            acc.y = fmaf(wt, f0.y, acc.y);
            acc.z = fmaf(wt, f1.x, acc.z);
            acc.w = fmaf(wt, f1.y, acc.w);
        }
    }
    float ss = acc.x * acc.x + acc.y * acc.y + acc.z * acc.z + acc.w * acc.w;
    for (int o = 16; o > 0; o >>= 1) ss += __shfl_xor_sync(0xffffffffu, ss, o);
    float inv = 1.0f / fmaxf(sqrtf(ss), 1e-12f);
    __half2 h0 = __floats2half2_rn(acc.x * inv, acc.y * inv);
    __half2 h1 = __floats2half2_rn(acc.z * inv, acc.w * inv);
    uint2 u;
    u.x = *(unsigned*)&h0;
    u.y = *(unsigned*)&h1;
    ((uint2*)g_xh)[w * 32 + lane] = u;
}

// ---------------- HMMA GEMM body (PDL-aware): Y = diag(isqrt)(A@B) ------------
template <bool PDL>
__device__ __forceinline__ void gemm_body(const __half* __restrict__ A,
                                          const __half* __restrict__ B,
                                          __half* __restrict__ Y) {
    __shared__ __align__(32) char smraw[49152];
    __half* sA = (__half*)smraw;
    __half* sB = (__half*)(smraw + 16384);
    float (*sC)[16][68] = reinterpret_cast<float(*)[16][68]>(smraw);

    int t = threadIdx.x;
    int row0 = blockIdx.x * 64;

    // weights first (independent of primary)
    #pragma unroll
    for (int q = 0; q < 8; q++) {
        int idx = t + q * 256;
        ((uint4*)sB)[idx] = ((const uint4*)B)[idx];
    }
    if (PDL) cudaGridDependencySynchronize();   // wait for producer of A
    #pragma unroll
    for (int q = 0; q < 4; q++) {
        int idx = t + q * 256;
        int r = idx >> 4, c4 = idx & 15;
        int gr = row0 + r;
        uint4 v = make_uint4(0u, 0u, 0u, 0u);
        if (gr < NN) v = ((const uint4*)A)[gr * 16 + c4];
        ((uint4*)sA)[idx] = v;
    }
    __syncthreads();

    int w = t >> 5, lane = t & 31;
    int wr = w >> 1, wc = w & 1;

    wmma::fragment<wmma::accumulator, 16, 16, 16, float> c[4];
    #pragma unroll
    for (int j = 0; j < 4; j++) wmma::fill_fragment(c[j], 0.f);

    #pragma unroll
    for (int k0 = 0; k0 < 8; k0++) {
        wmma::fragment<wmma::matrix_a, 16, 16, 16, half, wmma::row_major> a;
        wmma::load_matrix_sync(a, sA + (wr * 16) * 128 + k0 * 16, 128);
        #pragma unroll
        for (int j = 0; j < 4; j++) {
            wmma::fragment<wmma::matrix_b, 16, 16, 16, half, wmma::row_major> b;
            wmma::load_matrix_sync(b, sB + (k0 * 16) * 128 + wc * 64 + j * 16, 128);
            wmma::mma_sync(c[j], a, b, c[j]);
        }
    }
    __syncthreads();

    if (PDL) cudaTriggerProgrammaticLaunchCompletion();  // allow dependent launch

    #pragma unroll
    for (int j = 0; j < 4; j++)
        wmma::store_matrix_sync(&sC[w][0][j * 16], c[j], 68, wmma::mem_row_major);
    __syncwarp();
    int r = lane >> 1, ch = (lane & 1) * 32;
    int gr = row0 + wr * 16 + r;
    int col0 = wc * 64;
    if (gr < NN) {
        float sc = g_isqrt[gr];
        __align__(16) __half tmp[32];
        #pragma unroll
        for (int cc = 0; cc < 32; cc++)
            tmp[cc] = __float2half(sC[w][r][ch + cc] * sc);
        uint4* dstp = (uint4*)(Y + (size_t)gr * 128 + col0 + ch);
        const uint4* srcp = (const uint4*)tmp;
        #pragma unroll
        for (int q = 0; q < 4; q++) dstp[q] = srcp[q];
    }
}

__global__ __launch_bounds__(256) void k_gemmA(const __half* __restrict__ A,
                                               const __half* __restrict__ B,
                                               __half* __restrict__ Y) {
    gemm_body<false>(A, B, Y);
}
__global__ __launch_bounds__(256) void k_gemmA_pdl(const __half* __restrict__ A,
                                                   const __half* __restrict__ B,
                                                   __half* __restrict__ Y) {
    gemm_body<true>(A, B, Y);
}

// ---------------- gather core: out = isqrt_n * (sum_j y'_j + y'_n) -------------
__device__ __forceinline__ float4 agg_core(const uint2* __restrict__ in2, int n, int lane) {
    int lo = g_offs[n], hi = g_offs[n + 1];
    float4 acc = make_float4(0.f, 0.f, 0.f, 0.f);
    int p = lo;
    for (; p + 16 <= hi; p += 16) {
        int j[16];
        uint2 u[16];
        #pragma unroll
        for (int q = 0; q < 16; q++) j[q] = g_csr2[p + q].x;
        #pragma unroll
        for (int q = 0; q < 16; q++) u[q] = in2[j[q] * 32 + lane];
        #pragma unroll
        for (int q = 0; q < 16; q++) {
            float2 f0 = __half22float2(*(__half2*)&u[q].x);
            float2 f1 = __half22float2(*(__half2*)&u[q].y);
            acc.x += f0.x;
            acc.y += f0.y;
            acc.z += f1.x;
            acc.w += f1.y;
        }
    }
    for (; p + 8 <= hi; p += 8) {
        int j[8];
        uint2 u[8];
        #pragma unroll
        for (int q = 0; q < 8; q++) j[q] = g_csr2[p + q].x;
        #pragma unroll
        for (int q = 0; q < 8; q++) u[q] = in2[j[q] * 32 + lane];
        #pragma unroll
        for (int q = 0; q < 8; q++) {
            float2 f0 = __half22float2(*(__half2*)&u[q].x);
            float2 f1 = __half22float2(*(__half2*)&u[q].y);
            acc.x += f0.x;
            acc.y += f0.y;
            acc.z += f1.x;
            acc.w += f1.y;
        }
    }
    for (; p < hi; p++) {
        int jj = g_csr2[p].x;
        uint2 u = in2[jj * 32 + lane];
        float2 f0 = __half22float2(*(__half2*)&u.x);
        float2 f1 = __half22float2(*(__half2*)&u.y);
        acc.x += f0.x;
        acc.y += f0.y;
        acc.z += f1.x;
        acc.w += f1.y;
    }
    uint2 us = in2[n * 32 + lane];
    float2 s0 = __half22float2(*(__half2*)&us.x);
    float2 s1 = __half22float2(*(__half2*)&us.y);
    float si = g_isqrt[n];
    float4 o;
    o.x = (acc.x + s0.x) * si;
    o.y = (acc.y + s0.y) * si;
    o.z = (acc.z + s1.x) * si;
    o.w = (acc.w + s1.y) * si;
    return o;
}

// ---------------- agg + relu epilogue (primary of PDL chain) -------------------
__global__ void k_aggrelu(const __half* __restrict__ in, const float* __restrict__ b,
                          __half* __restrict__ out) {
    int w = (blockIdx.x * blockDim.x + threadIdx.x) >> 5;
    int lane = threadIdx.x & 31;
    if (w >= NN) {
        cudaTriggerProgrammaticLaunchCompletion();
        return;
    }
    float4 o = agg_core((const uint2*)in, w, lane);
    cudaTriggerProgrammaticLaunchCompletion();
    float4 bv = ((const float4*)b)[lane];
    o.x = fmaxf(o.x + bv.x, 0.f);
    o.y = fmaxf(o.y + bv.y, 0.f);
    o.z = fmaxf(o.z + bv.z, 0.f);
    o.w = fmaxf(o.w + bv.w, 0.f);
    __half2 h0 = __floats2half2_rn(o.x, o.y);
    __half2 h1 = __floats2half2_rn(o.z, o.w);
    uint2 u;
    u.x = *(unsigned*)&h0;
    u.y = *(unsigned*)&h1;
    ((uint2*)out)[w * 32 + lane] = u;
}

// ---------------- agg + z epilogue (PDL secondary + primary) -------------------
__global__ void k_aggz(const __half* __restrict__ in, const float* __restrict__ bmu,
                       const float* __restrict__ bls, const float* __restrict__ noise) {
    int w = (blockIdx.x * blockDim.x + threadIdx.x) >> 5;
    int lane = threadIdx.x & 31;
    cudaGridDependencySynchronize();           // wait for gemm2's y2
    if (w >= NN) {
        cudaTriggerProgrammaticLaunchCompletion();
        return;
    }
    float4 o = agg_core((const uint2*)in, w, lane);
    cudaTriggerProgrammaticLaunchCompletion();

    float4 e = make_float4(0.f, 0.f, 0.f, 0.f);
    if (lane >= 16) {
        float4 bv = ((const float4*)bls)[lane - 16];
        float4 nv = ((const float4*)(noise + (size_t)w * 64))[lane - 16];
        e.x = expf(o.x + bv.x) * nv.x;
        e.y = expf(o.y + bv.y) * nv.y;
        e.z = expf(o.z + bv.z) * nv.z;
        e.w = expf(o.w + bv.w) * nv.w;
    }
    e.x = __shfl_down_sync(0xffffffffu, e.x, 16);
    e.y = __shfl_down_sync(0xffffffffu, e.y, 16);
    e.z = __shfl_down_sync(0xffffffffu, e.z, 16);
    e.w = __shfl_down_sync(0xffffffffu, e.w, 16);
    if (lane < 16) {
        float4 bv = ((const float4*)bmu)[lane];
        float zx = o.x + bv.x + e.x;
        float zy = o.y + bv.y + e.y;
        float zz = o.z + bv.z + e.z;
        float zw = o.w + bv.w + e.w;
        __half2 h0 = __floats2half2_rn(zx, zy);
        __half2 h1 = __floats2half2_rn(zz, zw);
        uint2 u;
        u.x = *(unsigned*)&h0;
        u.y = *(unsigned*)&h1;
        ((uint2*)g_zh)[w * 16 + lane] = u;
    }
}

// ---------------- decoder (PDL secondary): cleanup preamble, then decode -------
__global__ void k_dec(float* __restrict__ out) {
    int gid = blockIdx.x * blockDim.x + threadIdx.x;
    if (gid < NN) g_cnt[gid] = 0;              // independent of aggz
    if (gid < NB) g_blkflag[gid] = 0;
    cudaGridDependencySynchronize();           // wait for z
    int n = gid >> 5;
    if (n >= NN) return;
    int lane = threadIdx.x & 31;
    int g = lane >> 3, sl = lane & 7;
    unsigned gm = 0xffu << (g * 8);

    int lo = g_offs[n], hi = g_offs[n + 1];
    uint4 zd = ((const uint4*)g_zh)[n * 8 + sl];
    float2 d0 = __half22float2(*(__half2*)&zd.x);
    float2 d1 = __half22float2(*(__half2*)&zd.y);
    float2 d2 = __half22float2(*(__half2*)&zd.z);
    float2 d3 = __half22float2(*(__half2*)&zd.w);

    for (int p = lo + g; p < hi; p += 8) {
        int pB = p + 4;
        bool hB = pB < hi;
        int2 eA = g_csr2[p];
        int2 eB = hB ? g_csr2[pB] : make_int2(0, 0);
        uint4 zA = ((const uint4*)g_zh)[eA.x * 8 + sl];
        uint4 zB = hB ? ((const uint4*)g_zh)[eB.x * 8 + sl] : make_uint4(0u, 0u, 0u, 0u);

        float2 a0 = __half22float2(*(__half2*)&zA.x);
        float2 a1 = __half22float2(*(__half2*)&zA.y);
        float2 a2 = __half22float2(*(__half2*)&zA.z);
        float2 a3 = __half22float2(*(__half2*)&zA.w);
        float vA = a0.x * d0.x + a0.y * d0.y + a1.x * d1.x + a1.y * d1.y
                 + a2.x * d2.x + a2.y * d2.y + a3.x * d3.x + a3.y * d3.y;

        float2 b0 = __half22float2(*(__half2*)&zB.x);
        float2 b1 = __half22float2(*(__half2*)&zB.y);
        float2 b2 = __half22float2(*(__half2*)&zB.z);
        float2 b3 = __half22float2(*(__half2*)&zB.w);
        float vB = b0.x * d0.x + b0.y * d0.y + b1.x * d1.x + b1.y * d1.y
                 + b2.x * d2.x + b2.y * d2.y + b3.x * d3.x + b3.y * d3.y;

        vA += __shfl_xor_sync(gm, vA, 4);
        vA += __shfl_xor_sync(gm, vA, 2);
        vA += __shfl_xor_sync(gm, vA, 1);
        vB += __shfl_xor_sync(gm, vB, 4);
        vB += __shfl_xor_sync(gm, vB, 2);
        vB += __shfl_xor_sync(gm, vB, 1);
        if (sl == 0) {
            out[eA.y] = vA;
            if (hB) out[eB.y] = vB;
        }
    }
}

// ---------------- launch -------------------------------------------------------
extern "C" void kernel_launch(void* const* d_in, const int* in_sizes, int n_in,
                              void* d_out, int out_size) {
    const int*   fidx  = (const int*)d_in[0];
    const int*   foff  = (const int*)d_in[1];
    const float* fw    = (const float*)d_in[2];
    const int*   edge  = (const int*)d_in[3];
    const float* noise = (const float*)d_in[4];
    const float* emb   = (const float*)d_in[5];
    const float* W1    = (const float*)d_in[6];
    const float* b1    = (const float*)d_in[7];
    const float* Wmu   = (const float*)d_in[8];
    const float* bmu   = (const float*)d_in[9];
    const float* Wls   = (const float*)d_in[10];
    const float* bls   = (const float*)d_in[11];
    float* out = (float*)d_out;

    const int* src = edge;
    const int* dst = edge + EE;

    __half *pxh = nullptr, *py = nullptr, *phh = nullptr, *pw1 = nullptr, *pwab = nullptr;
    cudaGetSymbolAddress((void**)&pxh, g_xh);
    cudaGetSymbolAddress((void**)&py, g_y);
    cudaGetSymbolAddress((void**)&phh, g_hh);
    cudaGetSymbolAddress((void**)&pw1, g_w1h);
    cudaGetSymbolAddress((void**)&pwab, g_wabh);

    static cudaStream_t s2 = nullptr;
    static cudaEvent_t evF = nullptr, evS = nullptr, evJ = nullptr;
    static bool ok = false;
    if (!s2) {
        ok = (cudaStreamCreateWithFlags(&s2, cudaStreamNonBlocking) == cudaSuccess) &&
             (cudaEventCreateWithFlags(&evF, cudaEventDisableTiming) == cudaSuccess) &&
             (cudaEventCreateWithFlags(&evS, cudaEventDisableTiming) == cudaSuccess) &&
             (cudaEventCreateWithFlags(&evJ, cudaEventDisableTiming) == cudaSuccess);
    }

    if (!ok) {
        k_hist<<<(EE / 4 + 255) / 256, 256>>>(dst);
        k_scan<<<NB, 1024>>>();
        k_scatter<<<(EE / 4 + 255) / 256, 256>>>(src, dst);
        k_cvtall<<<(VV * DD / 4 + 255) / 256, 256>>>(emb, W1, Wmu, Wls);
        k_embed<<<(NN + 3) / 4, 128>>>(fidx, foff, fw);
        k_gemmA<<<(NN + 63) / 64, 256>>>(pxh, pw1, py);
        k_aggrelu<<<(NN + 3) / 4, 128>>>(py, b1, phh);
        k_gemmA<<<(NN + 63) / 64, 256>>>(phh, pwab, py);
        k_aggz<<<(NN + 3) / 4, 128>>>(py, bmu, bls, noise);
        k_dec<<<(NN * 32 + 255) / 256, 256>>>(out);
        return;
    }

    // fork
    cudaEventRecord(evF, 0);
    cudaStreamWaitEvent(s2, evF, 0);

    // branch B (s2): fp16 conversions + embedding (no CSR dependence)
    k_cvtall<<<(VV * DD / 4 + 255) / 256, 256, 0, s2>>>(emb, W1, Wmu, Wls);
    k_embed<<<(NN + 3) / 4, 128, 0, s2>>>(fidx, foff, fw);

    // branch A (default): hist + scan (produces isqrt), then scatter
    k_hist<<<(EE / 4 + 255) / 256, 256>>>(dst);
    k_scan<<<NB, 1024>>>();
    cudaEventRecord(evS, 0);                 // isqrt ready
    k_scatter<<<(EE / 4 + 255) / 256, 256>>>(src, dst);

    // branch B continues: gemm1' needs isqrt (prescaled epilogue)
    cudaStreamWaitEvent(s2, evS, 0);
    k_gemmA<<<(NN + 63) / 64, 256, 0, s2>>>(pxh, pw1, py);   // y1' = isqrt*(x@W1)
    cudaEventRecord(evJ, s2);

    // join, then PDL-chained back half on stream 0
    cudaStreamWaitEvent(0, evJ, 0);

    k_aggrelu<<<(NN + 3) / 4, 128>>>(py, b1, phh);           // primary

    cudaLaunchAttribute pa;
    pa.id = cudaLaunchAttributeProgrammaticStreamSerialization;
    pa.val.programmaticStreamSerializationAllowed = 1;

    {   // gemm2 (PDL secondary of aggrelu)
        cudaLaunchConfig_t cfg = {};
        cfg.gridDim  = dim3((NN + 63) / 64, 1, 1);
        cfg.blockDim = dim3(256, 1, 1);
        cfg.dynamicSmemBytes = 0;
        cfg.stream = 0;
        cfg.attrs = &pa;
        cfg.numAttrs = 1;
        cudaLaunchKernelEx(&cfg, k_gemmA_pdl,
                           (const __half*)phh, (const __half*)pwab, (__half*)py);
    }
    {   // aggz (PDL secondary of gemm2)
        cudaLaunchConfig_t cfg = {};
        cfg.gridDim  = dim3((NN + 3) / 4, 1, 1);
        cfg.blockDim = dim3(128, 1, 1);
        cfg.dynamicSmemBytes = 0;
        cfg.stream = 0;
        cfg.attrs = &pa;
        cfg.numAttrs = 1;
        cudaLaunchKernelEx(&cfg, k_aggz,
                           (const __half*)py, bmu, bls, noise);
    }
    {   // dec (PDL secondary of aggz)
        cudaLaunchConfig_t cfg = {};
        cfg.gridDim  = dim3((NN * 32 + 255) / 256, 1, 1);
        cfg.blockDim = dim3(256, 1, 1);
        cfg.dynamicSmemBytes = 0;
        cfg.stream = 0;
        cfg.attrs = &pa;
        cfg.numAttrs = 1;
        cudaLaunchKernelEx(&cfg, k_dec, out);
    }
}